// round 14
// baseline (speedup 1.0000x reference)
#include <cuda_runtime.h>
#include <math.h>

typedef unsigned long long ULL;

// ---------------- static scratch (no allocations allowed) ----------------
__device__ __align__(16) float g_v[2 * 1024 * 64];      // vertex feats [B,N,64]
__device__ __align__(16) float g_f[2 * 2048 * 64];      // face feats   [B,F,64]
__device__ __align__(16) float g_X[2 * 4096 * 16];      // x buffer
__device__ __align__(16) float g_Y[2 * 8192 * 16];      // y buffer
__device__ float g_sp[256 * 64];
__device__ float g_sq[256 * 64];
__device__ float g_pool[2 * 64];

// ---------------- helpers ----------------
__device__ __forceinline__ float elu1(float x) { return x > 0.f ? x : expm1f(x); }

__device__ __forceinline__ ULL pk2(float s) {
    ULL r; asm("mov.b64 %0, {%1, %1};" : "=l"(r) : "f"(s)); return r;
}
__device__ __forceinline__ void fma2(ULL& d, ULL a, ULL b) {
    asm("fma.rn.f32x2 %0, %1, %2, %0;" : "+l"(d) : "l"(a), "l"(b));
}
__device__ __forceinline__ ULL add2(ULL a, ULL b) {
    ULL d; asm("add.rn.f32x2 %0, %1, %2;" : "=l"(d) : "l"(a), "l"(b)); return d;
}
__device__ __forceinline__ float2 up2(ULL v) {
    float2 r; asm("mov.b64 {%0, %1}, %2;" : "=f"(r.x), "=f"(r.y) : "l"(v)); return r;
}
__device__ __forceinline__ ULL shflx(ULL v, int m) {
    unsigned lo = (unsigned)v, hi = (unsigned)(v >> 32);
    lo = __shfl_xor_sync(0xffffffffu, lo, m);
    hi = __shfl_xor_sync(0xffffffffu, hi, m);
    return ((ULL)hi << 32) | lo;
}

// ---------------- init: v = inp@Win + b, fused elu-stats partials ----------------
__global__ void __launch_bounds__(256) k_init_v(const float* __restrict__ inp,
                                                const float* __restrict__ Win,
                                                const float* __restrict__ bin) {
    __shared__ float ss[256], qq[256];
    int tid = threadIdx.x, ch = tid & 63;
    float b = bin[ch], w0 = Win[ch], w1 = Win[64 + ch], w2 = Win[128 + ch];
    float s = 0.f, q = 0.f;
#pragma unroll
    for (int e = 0; e < 2; e++) {
        int idx = e * 65536 + blockIdx.x * 256 + tid;    // 256 blocks cover 131072
        int r = idx >> 6;
        float acc = fmaf(inp[r * 3 + 2], w2, fmaf(inp[r * 3 + 1], w1, fmaf(inp[r * 3], w0, b)));
        g_v[idx] = acc;
        float x = elu1(acc); s += x; q += x * x;
    }
    ss[tid] = s; qq[tid] = q;
    __syncthreads();
    if (tid < 64) {
#pragma unroll
        for (int j = 1; j < 4; j++) { s += ss[tid + 64 * j]; q += qq[tid + 64 * j]; }
        g_sp[blockIdx.x * 64 + tid] = s;
        g_sq[blockIdx.x * 64 + tid] = q;
    }
}

__global__ void k_zero(float* __restrict__ p, int n) {
    int i = blockIdx.x * 256 + threadIdx.x;
    if (i < n) p[i] = 0.f;
}

// ---------------- elu-stats partials over a tensor (for BN) ----------------
__global__ void __launch_bounds__(256) k_stats(const float* __restrict__ src, int rows) {
    __shared__ float ss[256], qq[256];
    int tid = threadIdx.x;
    int ch = tid & 63, g = tid >> 6;
    int slice = rows / gridDim.x;                        // gridDim.x = 64
    int r0 = blockIdx.x * slice;
    float s = 0.f, q = 0.f;
    for (int r = r0 + g; r < r0 + slice; r += 4) {
        float x = elu1(src[(size_t)r * 64 + ch]);
        s += x; q += x * x;
    }
    ss[tid] = s; qq[tid] = q;
    __syncthreads();
    if (g == 0) {
#pragma unroll
        for (int j = 1; j < 4; j++) { s += ss[ch + 64 * j]; q += qq[ch + 64 * j]; }
        g_sp[blockIdx.x * 64 + ch] = s;
        g_sq[blockIdx.x * 64 + ch] = q;
    }
}

// ---------------- elu -> BN -> 64x64 linear -> elu, BN coefs fused in ----------------
__global__ void __launch_bounds__(256) k_xform(const float* __restrict__ src,
                                               const float* __restrict__ W,
                                               const float* __restrict__ bias,
                                               const float* __restrict__ gamma,
                                               const float* __restrict__ beta,
                                               float invc, int nblk,
                                               float* __restrict__ dst) {
    __shared__ float Ws[64 * 64];
    __shared__ float ts[16][64];
    __shared__ float sa[64], sc[64];
    __shared__ float rs[256], rq[256];
    int tid = threadIdx.x;
    int ch = tid & 63, grp = tid >> 6;

    float s = 0.f, q = 0.f;
    for (int i = grp; i < nblk; i += 4) { s += g_sp[i * 64 + ch]; q += g_sq[i * 64 + ch]; }
    rs[tid] = s; rq[tid] = q;
    for (int i = tid; i < 4096; i += 256) Ws[i] = W[i];
    __syncthreads();
    if (tid < 64) {
#pragma unroll
        for (int j = 1; j < 4; j++) { s += rs[tid + 64 * j]; q += rq[tid + 64 * j]; }
        float m = s * invc;
        float var = q * invc - m * m;
        float a = gamma[tid] * rsqrtf(var + 1e-5f);
        sa[tid] = a;
        sc[tid] = beta[tid] - m * a;
    }
    __syncthreads();

    float a = sa[ch], c = sc[ch], bb = bias[ch];
    size_t base = (size_t)blockIdx.x * 1024;             // 16 rows * 64
#pragma unroll
    for (int j = 0; j < 4; j++) {
        float x = elu1(src[base + tid + 256 * j]);
        ts[grp + 4 * j][ch] = fmaf(x, a, c);
    }
    __syncthreads();
    float acc[4] = {bb, bb, bb, bb};
#pragma unroll
    for (int k = 0; k < 64; k++) {
        float w = Ws[k * 64 + ch];
#pragma unroll
        for (int j = 0; j < 4; j++) acc[j] = fmaf(ts[grp + 4 * j][k], w, acc[j]);
    }
#pragma unroll
    for (int j = 0; j < 4; j++) dst[base + tid + 256 * j] = elu1(acc[j]);
}

// ---------------- skinny GEMM: out += D[64-row tile, k-range] @ X ----------------
// grid (KS, M/64, B), block 128 (4 warps x 16 rows). Lane = rseg*8 + colh*4 + kq:
// thread owns rows 16w+4j+rseg (j 0..3), cols [8*colh, +8), k-eighth [8kq, +8)
// of each 32-k chunk. D: gmem -> registers, coalesced (4 kq-lanes cover a 128B
// row segment, 4 rseg rows per instr), never touches smem. X (2KB/chunk) in
// smem, row-repositioned layout: row k=8kq+i slot s at float off
// 64i + 16kq + 4*(s ^ (kq>>1)) -> reads hit 8 distinct granule-banks
// (conflict-free), stores at min wavefronts. Per-lane k-partials; 2-round kq
// butterfly at end; atomicAdd (spread REDG) into out. Double-buffered X,
// 2-chunk-ahead register prefetch for D.
__global__ void __launch_bounds__(128, 4) k_gemm(const float* __restrict__ D,
                                                 const float* __restrict__ X,
                                                 float* out,
                                                 int M, int K, int NC, int KS) {
    __shared__ __align__(16) float Xs[2][512];
    const int tid = threadIdx.x;
    const int l = tid & 31, w = tid >> 5;
    const int kq = l & 3, colh = (l >> 2) & 1, rseg = l >> 3;
    const int s = blockIdx.x, mt = blockIdx.y, b = blockIdx.z;
    const int c0 = (NC * s) / KS;
    const int nch = (NC * (s + 1)) / KS - c0;            // 64
    const float* Dg = D + ((size_t)b * M + (size_t)mt * 64 + 16 * w + rseg) * K
                        + c0 * 32 + 8 * kq;
    const float* Xg = X + ((size_t)b * K + (size_t)c0 * 32) * 16;

    // X staging map: thread t -> slot = t&3, kq_s = (t>>2)&3, i_s = t>>4
    const int sslot = tid & 3, skq = (tid >> 2) & 3, si = tid >> 4;
    const int ssrc = (8 * skq + si) * 16 + sslot * 4;                    // gmem float off
    const int sdst = 64 * si + 16 * skq + 4 * (sslot ^ (skq >> 1));      // smem float off

    // X read offsets (slot position = slot ^ (kq>>1), retrieves true slot's cols)
    const int xb0 = 16 * kq + 4 * ((colh * 2 + 0) ^ (kq >> 1));          // + 64*i
    const int xb1 = 16 * kq + 4 * ((colh * 2 + 1) ^ (kq >> 1));

    ULL acc[4][4];
#pragma unroll
    for (int j = 0; j < 4; j++)
#pragma unroll
        for (int u = 0; u < 4; u++) acc[j][u] = 0ULL;

    float4 db[2][8];
    float4 xr;

    // prologue: X(0) -> smem buf0, X(1) -> xr, D(0), D(1) -> regs
    {
        *(float4*)&Xs[0][sdst] = *(const float4*)(Xg + ssrc);
        xr = *(const float4*)(Xg + 512 + ssrc);
#pragma unroll
        for (int j = 0; j < 4; j++) {
            db[0][2 * j]     = *(const float4*)(Dg + (size_t)(4 * j) * K);
            db[0][2 * j + 1] = *(const float4*)(Dg + (size_t)(4 * j) * K + 4);
            db[1][2 * j]     = *(const float4*)(Dg + (size_t)(4 * j) * K + 32);
            db[1][2 * j + 1] = *(const float4*)(Dg + (size_t)(4 * j) * K + 36);
        }
    }

    for (int c = 0; c < nch; c++) {
        __syncthreads();    // stores of Xs[c&1] visible; all done computing c-1
        if (c + 1 < nch) *(float4*)&Xs[(c + 1) & 1][sdst] = xr;
        const float* xsm = Xs[c & 1];
        const int cb = c & 1;
#pragma unroll
        for (int i = 0; i < 8; i++) {
            ulonglong2 x0 = *(const ulonglong2*)&xsm[64 * i + xb0];
            ulonglong2 x1 = *(const ulonglong2*)&xsm[64 * i + xb1];
#pragma unroll
            for (int j = 0; j < 4; j++) {
                float4 dv = db[cb][2 * j + (i >> 2)];
                float d = (i & 3) == 0 ? dv.x : (i & 3) == 1 ? dv.y
                        : (i & 3) == 2 ? dv.z : dv.w;
                ULL wv = pk2(d);
                fma2(acc[j][0], wv, x0.x); fma2(acc[j][1], wv, x0.y);
                fma2(acc[j][2], wv, x1.x); fma2(acc[j][3], wv, x1.y);
            }
        }
        if (c + 2 < nch) {
            xr = *(const float4*)(Xg + (c + 2) * 512 + ssrc);
#pragma unroll
            for (int j = 0; j < 4; j++) {
                db[cb][2 * j]     = *(const float4*)(Dg + (size_t)(4 * j) * K + (c + 2) * 32);
                db[cb][2 * j + 1] = *(const float4*)(Dg + (size_t)(4 * j) * K + (c + 2) * 32 + 4);
            }
        }
    }

    // butterfly over kq lanes (bits 0-1); all lanes end with full k-range sums
#pragma unroll
    for (int j = 0; j < 4; j++)
#pragma unroll
        for (int u = 0; u < 4; u++) {
            acc[j][u] = add2(acc[j][u], shflx(acc[j][u], 1));
            acc[j][u] = add2(acc[j][u], shflx(acc[j][u], 2));
        }

    // lane's kq selects which of its 4 rows to write (j = kq); 8 cols via colh
    float* p = out + ((size_t)b * M + (size_t)mt * 64 + 16 * w + 4 * kq + rseg) * 16
                   + 8 * colh;
#pragma unroll
    for (int u = 0; u < 4; u++) {
        float2 a = up2(acc[kq][u]);
        atomicAdd(p + 2 * u,     a.x);
        atomicAdd(p + 2 * u + 1, a.y);
    }
}

// ---------------- epilogue ----------------
__global__ void k_pool(const float* __restrict__ t, const float* __restrict__ mask) {
    __shared__ float ss[256], ms[256];
    int b = blockIdx.x;
    int ch = threadIdx.x & 63, g = threadIdx.x >> 6;
    float s = 0.f, m = 0.f;
    for (int n = g; n < 1024; n += 4) {
        float mv = mask[b * 1024 + n];
        s += t[((size_t)b * 1024 + n) * 64 + ch] * mv;
        m += mv;
    }
    ss[threadIdx.x] = s; ms[threadIdx.x] = m;
    __syncthreads();
    if (g == 0) {
#pragma unroll
        for (int j = 1; j < 4; j++) { s += ss[ch + 64 * j]; m += ms[ch + 64 * j]; }
        g_pool[b * 64 + ch] = s / m;
    }
}

__global__ void k_head(const float* __restrict__ Wfc, const float* __restrict__ bfc,
                       float* __restrict__ out) {
    __shared__ float lg[2][10];
    int tid = threadIdx.x;
    if (tid < 20) {
        int b = tid / 10, j = tid % 10;
        float acc = bfc[j];
        for (int ch = 0; ch < 64; ch++) acc = fmaf(g_pool[b * 64 + ch], Wfc[ch * 10 + j], acc);
        lg[b][j] = acc;
    }
    __syncthreads();
    if (tid < 20) {
        int b = tid / 10, j = tid % 10;
        float mx = -1e30f;
        for (int t = 0; t < 10; t++) mx = fmaxf(mx, lg[b][t]);
        float se = 0.f;
        for (int t = 0; t < 10; t++) se += expf(lg[b][t] - mx);
        out[b * 10 + j] = lg[b][j] - mx - logf(se);
    }
}

// ---------------- launcher ----------------
extern "C" void kernel_launch(void* const* d_in, const int* in_sizes, int n_in,
                              void* d_out, int out_size) {
    const float* inp  = (const float*)d_in[0];
    const float* Di   = (const float*)d_in[1];
    const float* DiA  = (const float*)d_in[2];
    const float* mask = (const float*)d_in[3];
    const float* W_in = (const float*)d_in[4];
    const float* b_in = (const float*)d_in[5];
    const float* rnW0 = (const float*)d_in[6];
    const float* rnb0 = (const float*)d_in[7];
    const float* rng0 = (const float*)d_in[8];
    const float* rnbe0= (const float*)d_in[9];
    const float* rnW1 = (const float*)d_in[10];
    const float* rnb1 = (const float*)d_in[11];
    const float* rng1 = (const float*)d_in[12];
    const float* rnbe1= (const float*)d_in[13];
    const float* bn2g = (const float*)d_in[14];
    const float* bn2b = (const float*)d_in[15];
    const float* W2   = (const float*)d_in[16];
    const float* b2   = (const float*)d_in[17];
    const float* Wfc  = (const float*)d_in[18];
    const float* bfc  = (const float*)d_in[19];
    float* out = (float*)d_out;

    float *v, *f, *X, *Y;
    cudaGetSymbolAddress((void**)&v, g_v);
    cudaGetSymbolAddress((void**)&f, g_f);
    cudaGetSymbolAddress((void**)&X, g_X);
    cudaGetSymbolAddress((void**)&Y, g_Y);

    k_init_v<<<256, 256>>>(inp, W_in, b_in);             // #1  (v + bn stats partials)
    k_zero<<<1024, 256>>>(f, 2 * 2048 * 64);             // #2

    int nblk_v = 256;
    for (int i = 0; i < 5; i++) {
        // vertex -> face
        k_xform<<<128, 256>>>(v, rnW0 + i * 4096, rnb0 + i * 64,
                              rng0 + i * 64, rnbe0 + i * 64,
                              1.f / 2048.f, nblk_v, X);  // #3 (gemm is #4 for ncu)
        k_gemm<<<dim3(2, 128, 2), 128>>>(Di, X, f, 8192, 4096, 128, 2);
        k_stats<<<64, 256>>>(f, 4096);
        // face -> vertex
        k_xform<<<256, 256>>>(f, rnW1 + i * 4096, rnb1 + i * 64,
                              rng1 + i * 64, rnbe1 + i * 64,
                              1.f / 4096.f, 64, Y);
        k_gemm<<<dim3(4, 64, 2), 128>>>(DiA, Y, v, 4096, 8192, 256, 4);
        k_stats<<<64, 256>>>(v, 2048);
        nblk_v = 64;
    }

    // epilogue
    k_xform<<<128, 256>>>(v, W2, b2, bn2g, bn2b, 1.f / 2048.f, nblk_v, Y);
    k_pool<<<2, 256>>>(Y, mask);
    k_head<<<1, 32>>>(Wfc, bfc, out);
}

// round 15
// speedup vs baseline: 2.3562x; 2.3562x over previous
#include <cuda_runtime.h>
#include <math.h>

typedef unsigned long long ULL;

// ---------------- static scratch (no allocations allowed) ----------------
__device__ __align__(16) float g_v[2 * 1024 * 64];      // vertex feats [B,N,64]
__device__ __align__(16) float g_f[2 * 2048 * 64];      // face feats   [B,F,64]
__device__ __align__(16) float g_X[2 * 4096 * 16];      // x buffer
__device__ __align__(16) float g_Y[2 * 8192 * 16];      // y buffer
__device__ float g_sp[256 * 64];
__device__ float g_sq[256 * 64];
__device__ float g_pool[2 * 64];

// ---------------- helpers ----------------
__device__ __forceinline__ float elu1(float x) { return x > 0.f ? x : expm1f(x); }

__device__ __forceinline__ ULL pk2(float s) {
    ULL r; asm("mov.b64 %0, {%1, %1};" : "=l"(r) : "f"(s)); return r;
}
__device__ __forceinline__ void fma2(ULL& d, ULL a, ULL b) {
    asm("fma.rn.f32x2 %0, %1, %2, %0;" : "+l"(d) : "l"(a), "l"(b));
}
__device__ __forceinline__ float2 up2(ULL v) {
    float2 r; asm("mov.b64 {%0, %1}, %2;" : "=f"(r.x), "=f"(r.y) : "l"(v)); return r;
}
__device__ __forceinline__ void cpa16(unsigned dst, const float* src) {
    asm volatile("cp.async.cg.shared.global [%0], [%1], 16;" :: "r"(dst), "l"(src));
}

// ---------------- init: v = inp@Win + b, fused elu-stats partials + f zero ----------------
__global__ void __launch_bounds__(256) k_init_v(const float* __restrict__ inp,
                                                const float* __restrict__ Win,
                                                const float* __restrict__ bin) {
    __shared__ float ss[256], qq[256];
    int tid = threadIdx.x, ch = tid & 63;
    float b = bin[ch], w0 = Win[ch], w1 = Win[64 + ch], w2 = Win[128 + ch];
    float s = 0.f, q = 0.f;
#pragma unroll
    for (int e = 0; e < 2; e++) {
        int idx = e * 65536 + blockIdx.x * 256 + tid;    // 256 blocks cover 131072
        int r = idx >> 6;
        float acc = fmaf(inp[r * 3 + 2], w2, fmaf(inp[r * 3 + 1], w1, fmaf(inp[r * 3], w0, b)));
        g_v[idx] = acc;
        float x = elu1(acc); s += x; q += x * x;
    }
    // zero f: 262144 floats = 65536 float4 = gridDim(256) * 256 threads
    ((float4*)g_f)[blockIdx.x * 256 + tid] = make_float4(0.f, 0.f, 0.f, 0.f);
    ss[tid] = s; qq[tid] = q;
    __syncthreads();
    if (tid < 64) {
#pragma unroll
        for (int j = 1; j < 4; j++) { s += ss[tid + 64 * j]; q += qq[tid + 64 * j]; }
        g_sp[blockIdx.x * 64 + tid] = s;
        g_sq[blockIdx.x * 64 + tid] = q;
    }
}

// ---------------- elu-stats partials over a tensor (for BN), 16 blocks ----------------
__global__ void __launch_bounds__(256) k_stats(const float* __restrict__ src, int rows) {
    __shared__ float ss[256], qq[256];
    int tid = threadIdx.x;
    int ch = tid & 63, g = tid >> 6;
    int slice = rows / gridDim.x;                        // gridDim.x = 16
    int r0 = blockIdx.x * slice;
    float s = 0.f, q = 0.f;
    for (int r = r0 + g; r < r0 + slice; r += 4) {
        float x = elu1(src[(size_t)r * 64 + ch]);
        s += x; q += x * x;
    }
    ss[tid] = s; qq[tid] = q;
    __syncthreads();
    if (g == 0) {
#pragma unroll
        for (int j = 1; j < 4; j++) { s += ss[ch + 64 * j]; q += qq[ch + 64 * j]; }
        g_sp[blockIdx.x * 64 + ch] = s;
        g_sq[blockIdx.x * 64 + ch] = q;
    }
}

// ---------------- elu -> BN -> 64x64 linear -> elu, BN coefs fused in ----------------
__global__ void __launch_bounds__(256) k_xform(const float* __restrict__ src,
                                               const float* __restrict__ W,
                                               const float* __restrict__ bias,
                                               const float* __restrict__ gamma,
                                               const float* __restrict__ beta,
                                               float invc, int nblk,
                                               float* __restrict__ dst) {
    __shared__ float Ws[64 * 64];
    __shared__ float ts[16][64];
    __shared__ float sa[64], sc[64];
    __shared__ float rs[256], rq[256];
    int tid = threadIdx.x;
    int ch = tid & 63, grp = tid >> 6;

    float s = 0.f, q = 0.f;
    for (int i = grp; i < nblk; i += 4) { s += g_sp[i * 64 + ch]; q += g_sq[i * 64 + ch]; }
    rs[tid] = s; rq[tid] = q;
    for (int i = tid; i < 4096; i += 256) Ws[i] = W[i];
    __syncthreads();
    if (tid < 64) {
#pragma unroll
        for (int j = 1; j < 4; j++) { s += rs[tid + 64 * j]; q += rq[tid + 64 * j]; }
        float m = s * invc;
        float var = q * invc - m * m;
        float a = gamma[tid] * rsqrtf(var + 1e-5f);
        sa[tid] = a;
        sc[tid] = beta[tid] - m * a;
    }
    __syncthreads();

    float a = sa[ch], c = sc[ch], bb = bias[ch];
    size_t base = (size_t)blockIdx.x * 1024;             // 16 rows * 64
#pragma unroll
    for (int j = 0; j < 4; j++) {
        float x = elu1(src[base + tid + 256 * j]);
        ts[grp + 4 * j][ch] = fmaf(x, a, c);
    }
    __syncthreads();
    float acc[4] = {bb, bb, bb, bb};
#pragma unroll
    for (int k = 0; k < 64; k++) {
        float w = Ws[k * 64 + ch];
#pragma unroll
        for (int j = 0; j < 4; j++) acc[j] = fmaf(ts[grp + 4 * j][k], w, acc[j]);
    }
#pragma unroll
    for (int j = 0; j < 4; j++) dst[base + tid + 256 * j] = elu1(acc[j]);
}

// ---------------- skinny GEMM: out += D[128-row tile, k-range] @ X ----------------
// grid (KS, M/128, B), block 128, 36 KB dyn smem -> 6 CTAs/SM, single wave.
// 32-k chunks (128B/row), cpa16 staging with 16B XOR swizzle (granule g^(rb&7),
// per-thread constant). Reads: per kq one LDS.128 per row, granule kq^rl ->
// 8 distinct granules x 8 rows cover all 32 banks (conflict-free, q broadcast).
// Thread owns 4 rows (rl+32j) x 4 cols. Uneven split-K over 32-k chunk columns.
// Epilogue: atomicAdd (REDG) straight into out -- no split-K partials.
__global__ void __launch_bounds__(128) k_gemm(const float* __restrict__ D,
                                              const float* __restrict__ X,
                                              float* out,
                                              int M, int K, int NC, int KS) {
    extern __shared__ __align__(16) float smem[];
    float* Ds = smem;                                    // 2 x 128 x 32
    float* Xs = smem + 8192;                             // 2 x 32 x 16
    const int tid = threadIdx.x;
    const int s = blockIdx.x, mt = blockIdx.y, b = blockIdx.z;
    const int c0 = (NC * s) / KS;
    const int nch = (NC * (s + 1)) / KS - c0;
    const float* Dg = D + ((size_t)b * M + (size_t)mt * 128) * K + c0 * 32;
    const float* Xg = X + ((size_t)b * K + (size_t)c0 * 32) * 16;

    unsigned dsb = (unsigned)__cvta_generic_to_shared(Ds);
    unsigned xsb = (unsigned)__cvta_generic_to_shared(Xs);

    const int g = tid & 7, rb = tid >> 3;                // staging granule / row base
    const unsigned gsw = 16u * (unsigned)(g ^ (rb & 7)); // per-thread constant swizzle

    auto issue = [&](int c, int buf) {
        unsigned dd = dsb + buf * 16384u;
        const float* src = Dg + c * 32 + g * 4;
#pragma unroll
        for (int j = 0; j < 8; j++) {
            int r = rb + 16 * j;
            cpa16(dd + (unsigned)(r * 128) + gsw, src + (size_t)r * K);
        }
        cpa16(xsb + buf * 2048u + tid * 16u, Xg + c * 512 + tid * 4);
        asm volatile("cp.async.commit_group;");
    };

    ULL acc[4][2];
#pragma unroll
    for (int j = 0; j < 4; j++) { acc[j][0] = 0ULL; acc[j][1] = 0ULL; }

    const int q = tid & 3, rl = tid >> 2;                // compute: col group, row lane

    issue(0, 0);

    for (int c = 0; c < nch; c++) {
        if (c + 1 < nch) {
            issue(c + 1, (c + 1) & 1);
            asm volatile("cp.async.wait_group 1;");
        } else {
            asm volatile("cp.async.wait_group 0;");
        }
        __syncthreads();
        const float* dsm = Ds + (c & 1) * 4096;
        const float* xsm = Xs + (c & 1) * 512;
#pragma unroll
        for (int kq = 0; kq < 8; kq++) {
            ulonglong2 xv[4];
#pragma unroll
            for (int dk = 0; dk < 4; dk++)
                xv[dk] = *(const ulonglong2*)&xsm[(kq * 4 + dk) * 16 + q * 4];
#pragma unroll
            for (int j = 0; j < 4; j++) {
                int r = rl + 32 * j;
                float4 d = *(const float4*)&dsm[r * 32 + 4 * (kq ^ (r & 7))];
                ULL w0 = pk2(d.x), w1 = pk2(d.y), w2 = pk2(d.z), w3 = pk2(d.w);
                fma2(acc[j][0], w0, xv[0].x); fma2(acc[j][1], w0, xv[0].y);
                fma2(acc[j][0], w1, xv[1].x); fma2(acc[j][1], w1, xv[1].y);
                fma2(acc[j][0], w2, xv[2].x); fma2(acc[j][1], w2, xv[2].y);
                fma2(acc[j][0], w3, xv[3].x); fma2(acc[j][1], w3, xv[3].y);
            }
        }
        __syncthreads();
    }

    // accumulate straight into the output tensor (REDG, no partials)
    float* ob = out + ((size_t)b * M + (size_t)mt * 128) * 16;
#pragma unroll
    for (int j = 0; j < 4; j++) {
        float* p = ob + (rl + 32 * j) * 16 + q * 4;
        float2 a0 = up2(acc[j][0]);
        float2 a1 = up2(acc[j][1]);
        atomicAdd(p + 0, a0.x);
        atomicAdd(p + 1, a0.y);
        atomicAdd(p + 2, a1.x);
        atomicAdd(p + 3, a1.y);
    }
}

// ---------------- epilogue ----------------
__global__ void k_pool(const float* __restrict__ t, const float* __restrict__ mask) {
    __shared__ float ss[256], ms[256];
    int b = blockIdx.x;
    int ch = threadIdx.x & 63, g = threadIdx.x >> 6;
    float s = 0.f, m = 0.f;
    for (int n = g; n < 1024; n += 4) {
        float mv = mask[b * 1024 + n];
        s += t[((size_t)b * 1024 + n) * 64 + ch] * mv;
        m += mv;
    }
    ss[threadIdx.x] = s; ms[threadIdx.x] = m;
    __syncthreads();
    if (g == 0) {
#pragma unroll
        for (int j = 1; j < 4; j++) { s += ss[ch + 64 * j]; m += ms[ch + 64 * j]; }
        g_pool[b * 64 + ch] = s / m;
    }
}

__global__ void k_head(const float* __restrict__ Wfc, const float* __restrict__ bfc,
                       float* __restrict__ out) {
    __shared__ float lg[2][10];
    int tid = threadIdx.x;
    if (tid < 20) {
        int b = tid / 10, j = tid % 10;
        float acc = bfc[j];
        for (int ch = 0; ch < 64; ch++) acc = fmaf(g_pool[b * 64 + ch], Wfc[ch * 10 + j], acc);
        lg[b][j] = acc;
    }
    __syncthreads();
    if (tid < 20) {
        int b = tid / 10, j = tid % 10;
        float mx = -1e30f;
        for (int t = 0; t < 10; t++) mx = fmaxf(mx, lg[b][t]);
        float se = 0.f;
        for (int t = 0; t < 10; t++) se += expf(lg[b][t] - mx);
        out[b * 10 + j] = lg[b][j] - mx - logf(se);
    }
}

// ---------------- launcher ----------------
extern "C" void kernel_launch(void* const* d_in, const int* in_sizes, int n_in,
                              void* d_out, int out_size) {
    const float* inp  = (const float*)d_in[0];
    const float* Di   = (const float*)d_in[1];
    const float* DiA  = (const float*)d_in[2];
    const float* mask = (const float*)d_in[3];
    const float* W_in = (const float*)d_in[4];
    const float* b_in = (const float*)d_in[5];
    const float* rnW0 = (const float*)d_in[6];
    const float* rnb0 = (const float*)d_in[7];
    const float* rng0 = (const float*)d_in[8];
    const float* rnbe0= (const float*)d_in[9];
    const float* rnW1 = (const float*)d_in[10];
    const float* rnb1 = (const float*)d_in[11];
    const float* rng1 = (const float*)d_in[12];
    const float* rnbe1= (const float*)d_in[13];
    const float* bn2g = (const float*)d_in[14];
    const float* bn2b = (const float*)d_in[15];
    const float* W2   = (const float*)d_in[16];
    const float* b2   = (const float*)d_in[17];
    const float* Wfc  = (const float*)d_in[18];
    const float* bfc  = (const float*)d_in[19];
    float* out = (float*)d_out;

    float *v, *f, *X, *Y;
    cudaGetSymbolAddress((void**)&v, g_v);
    cudaGetSymbolAddress((void**)&f, g_f);
    cudaGetSymbolAddress((void**)&X, g_X);
    cudaGetSymbolAddress((void**)&Y, g_Y);

    const int SMEM = (8192 + 1024) * 4;                  // 36 KB dynamic
    cudaFuncSetAttribute(k_gemm, cudaFuncAttributeMaxDynamicSharedMemorySize, SMEM);

    k_init_v<<<256, 256>>>(inp, W_in, b_in);             // #1  (v + f zero + stats partials)

    int nblk_v = 256;
    for (int i = 0; i < 5; i++) {
        // vertex -> face
        k_xform<<<128, 256>>>(v, rnW0 + i * 4096, rnb0 + i * 64,
                              rng0 + i * 64, rnbe0 + i * 64,
                              1.f / 2048.f, nblk_v, X);
        k_gemm<<<dim3(6, 64, 2), 128, SMEM>>>(Di, X, f, 8192, 4096, 128, 6);
        k_stats<<<16, 256>>>(f, 4096);
        // face -> vertex
        k_xform<<<256, 256>>>(f, rnW1 + i * 4096, rnb1 + i * 64,
                              rng1 + i * 64, rnbe1 + i * 64,
                              1.f / 4096.f, 16, Y);
        k_gemm<<<dim3(12, 32, 2), 128, SMEM>>>(DiA, Y, v, 4096, 8192, 256, 12);
        k_stats<<<16, 256>>>(v, 2048);
        nblk_v = 16;
    }

    // epilogue
    k_xform<<<128, 256>>>(v, W2, b2, bn2g, bn2b, 1.f / 2048.f, nblk_v, Y);
    k_pool<<<2, 256>>>(Y, mask);
    k_head<<<1, 32>>>(Wfc, bfc, out);
}

// round 17
// speedup vs baseline: 2.4683x; 1.0476x over previous
#include <cuda_runtime.h>
#include <math.h>

typedef unsigned long long ULL;

// ---------------- static scratch (no allocations allowed) ----------------
__device__ __align__(16) float g_v[2 * 1024 * 64];      // vertex feats [B,N,64]
__device__ __align__(16) float g_f[2 * 2048 * 64];      // face feats   [B,F,64]
__device__ __align__(16) float g_X[2 * 4096 * 16];      // x buffer
__device__ __align__(16) float g_Y[2 * 8192 * 16];      // y buffer
__device__ float g_sp[256 * 64];
__device__ float g_sq[256 * 64];
__device__ float g_pool[2 * 64];

// ---------------- helpers ----------------
__device__ __forceinline__ float elu1(float x) { return x > 0.f ? x : expm1f(x); }

__device__ __forceinline__ ULL pk2(float s) {
    ULL r; asm("mov.b64 %0, {%1, %1};" : "=l"(r) : "f"(s)); return r;
}
__device__ __forceinline__ void fma2(ULL& d, ULL a, ULL b) {
    asm("fma.rn.f32x2 %0, %1, %2, %0;" : "+l"(d) : "l"(a), "l"(b));
}
__device__ __forceinline__ float2 up2(ULL v) {
    float2 r; asm("mov.b64 {%0, %1}, %2;" : "=f"(r.x), "=f"(r.y) : "l"(v)); return r;
}
__device__ __forceinline__ void cpa16(unsigned dst, const float* src) {
    asm volatile("cp.async.cg.shared.global [%0], [%1], 16;" :: "r"(dst), "l"(src));
}

// ---------------- init: v = inp@Win + b, fused elu-stats partials + f zero ----------------
__global__ void __launch_bounds__(256) k_init_v(const float* __restrict__ inp,
                                                const float* __restrict__ Win,
                                                const float* __restrict__ bin) {
    __shared__ float ss[256], qq[256];
    int tid = threadIdx.x, ch = tid & 63;
    float b = bin[ch], w0 = Win[ch], w1 = Win[64 + ch], w2 = Win[128 + ch];
    float s = 0.f, q = 0.f;
#pragma unroll
    for (int e = 0; e < 2; e++) {
        int idx = e * 65536 + blockIdx.x * 256 + tid;    // 256 blocks cover 131072
        int r = idx >> 6;
        float acc = fmaf(inp[r * 3 + 2], w2, fmaf(inp[r * 3 + 1], w1, fmaf(inp[r * 3], w0, b)));
        g_v[idx] = acc;
        float x = elu1(acc); s += x; q += x * x;
    }
    // zero f: 262144 floats = 65536 float4 = 256 blocks * 256 threads
    ((float4*)g_f)[blockIdx.x * 256 + tid] = make_float4(0.f, 0.f, 0.f, 0.f);
    ss[tid] = s; qq[tid] = q;
    __syncthreads();
    if (tid < 64) {
#pragma unroll
        for (int j = 1; j < 4; j++) { s += ss[tid + 64 * j]; q += qq[tid + 64 * j]; }
        g_sp[blockIdx.x * 64 + tid] = s;
        g_sq[blockIdx.x * 64 + tid] = q;
    }
}

// ---------------- elu-stats partials, vectorized (64 blocks) ----------------
// thread t = (quad = t&15 -> channels 4q..4q+3, row lane = t>>4), float4 loads.
__global__ void __launch_bounds__(256) k_stats(const float* __restrict__ src, int rows) {
    __shared__ float4 s4[256], q4[256];
    int tid = threadIdx.x;
    int quad = tid & 15, rl = tid >> 4;                  // 16 quads x 16 row lanes
    int rpb = rows >> 6;                                 // rows per block (64 blocks)
    int r0 = blockIdx.x * rpb;
    float4 s = make_float4(0.f, 0.f, 0.f, 0.f);
    float4 q = make_float4(0.f, 0.f, 0.f, 0.f);
    for (int r = rl; r < rpb; r += 16) {
        float4 x = *(const float4*)(src + ((size_t)(r0 + r) << 6) + quad * 4);
        x.x = elu1(x.x); x.y = elu1(x.y); x.z = elu1(x.z); x.w = elu1(x.w);
        s.x += x.x; s.y += x.y; s.z += x.z; s.w += x.w;
        q.x += x.x * x.x; q.y += x.y * x.y; q.z += x.z * x.z; q.w += x.w * x.w;
    }
    s4[tid] = s; q4[tid] = q;
    __syncthreads();
    if (tid < 64) {                                      // tid = quad*4 + e
        int qd = tid >> 2, e = tid & 3;
        float ps = 0.f, pq = 0.f;
#pragma unroll
        for (int m = 0; m < 16; m++) {
            const float* sp = (const float*)&s4[qd + 16 * m];
            const float* qp = (const float*)&q4[qd + 16 * m];
            ps += sp[e]; pq += qp[e];
        }
        g_sp[blockIdx.x * 64 + tid] = ps;                // channel = 4*qd + e = tid
        g_sq[blockIdx.x * 64 + tid] = pq;
    }
}

// ---------------- elu -> BN -> 64x64 linear -> elu, BN coefs fused in ----------------
__global__ void __launch_bounds__(256) k_xform(const float* __restrict__ src,
                                               const float* __restrict__ W,
                                               const float* __restrict__ bias,
                                               const float* __restrict__ gamma,
                                               const float* __restrict__ beta,
                                               float invc, int nblk,
                                               float* __restrict__ dst) {
    __shared__ float Ws[64 * 64];
    __shared__ float ts[16][64];
    __shared__ float sa[64], sc[64];
    __shared__ float rs[256], rq[256];
    int tid = threadIdx.x;
    int ch = tid & 63, grp = tid >> 6;

    float s = 0.f, q = 0.f;
    for (int i = grp; i < nblk; i += 4) { s += g_sp[i * 64 + ch]; q += g_sq[i * 64 + ch]; }
    rs[tid] = s; rq[tid] = q;
    for (int i = tid; i < 4096; i += 256) Ws[i] = W[i];
    __syncthreads();
    if (tid < 64) {
#pragma unroll
        for (int j = 1; j < 4; j++) { s += rs[tid + 64 * j]; q += rq[tid + 64 * j]; }
        float m = s * invc;
        float var = q * invc - m * m;
        float a = gamma[tid] * rsqrtf(var + 1e-5f);
        sa[tid] = a;
        sc[tid] = beta[tid] - m * a;
    }
    __syncthreads();

    float a = sa[ch], c = sc[ch], bb = bias[ch];
    size_t base = (size_t)blockIdx.x * 1024;             // 16 rows * 64
#pragma unroll
    for (int j = 0; j < 4; j++) {
        float x = elu1(src[base + tid + 256 * j]);
        ts[grp + 4 * j][ch] = fmaf(x, a, c);
    }
    __syncthreads();
    float acc[4] = {bb, bb, bb, bb};
#pragma unroll
    for (int k = 0; k < 64; k++) {
        float w = Ws[k * 64 + ch];
#pragma unroll
        for (int j = 0; j < 4; j++) acc[j] = fmaf(ts[grp + 4 * j][k], w, acc[j]);
    }
#pragma unroll
    for (int j = 0; j < 4; j++) dst[base + tid + 256 * j] = elu1(acc[j]);
}

// ---------------- skinny GEMM: out += D[128-row tile, k-range] @ X ----------------
// grid (KS, M/128, B), block 128, 36 KB dyn smem -> 6 CTAs/SM, single wave.
// 32-k chunks (128B/row), cpa16 staging with 16B XOR swizzle (granule g^(rb&7),
// per-thread constant). Reads: per kq one LDS.128 per row, granule kq^rl ->
// 8 distinct granules x 8 rows cover all 32 banks (conflict-free, q broadcast).
// Thread owns 4 rows (rl+32j) x 4 cols. Uneven split-K over 32-k chunk columns.
// Epilogue: atomicAdd (REDG) straight into out -- no split-K partials.
__global__ void __launch_bounds__(128) k_gemm(const float* __restrict__ D,
                                              const float* __restrict__ X,
                                              float* out,
                                              int M, int K, int NC, int KS) {
    extern __shared__ __align__(16) float smem[];
    float* Ds = smem;                                    // 2 x 128 x 32
    float* Xs = smem + 8192;                             // 2 x 32 x 16
    const int tid = threadIdx.x;
    const int s = blockIdx.x, mt = blockIdx.y, b = blockIdx.z;
    const int c0 = (NC * s) / KS;
    const int nch = (NC * (s + 1)) / KS - c0;
    const float* Dg = D + ((size_t)b * M + (size_t)mt * 128) * K + c0 * 32;
    const float* Xg = X + ((size_t)b * K + (size_t)c0 * 32) * 16;

    unsigned dsb = (unsigned)__cvta_generic_to_shared(Ds);
    unsigned xsb = (unsigned)__cvta_generic_to_shared(Xs);

    const int g = tid & 7, rb = tid >> 3;                // staging granule / row base
    const unsigned gsw = 16u * (unsigned)(g ^ (rb & 7)); // per-thread constant swizzle

    auto issue = [&](int c, int buf) {
        unsigned dd = dsb + buf * 16384u;
        const float* src = Dg + c * 32 + g * 4;
#pragma unroll
        for (int j = 0; j < 8; j++) {
            int r = rb + 16 * j;
            cpa16(dd + (unsigned)(r * 128) + gsw, src + (size_t)r * K);
        }
        cpa16(xsb + buf * 2048u + tid * 16u, Xg + c * 512 + tid * 4);
        asm volatile("cp.async.commit_group;");
    };

    ULL acc[4][2];
#pragma unroll
    for (int j = 0; j < 4; j++) { acc[j][0] = 0ULL; acc[j][1] = 0ULL; }

    const int q = tid & 3, rl = tid >> 2;                // compute: col group, row lane

    issue(0, 0);

    for (int c = 0; c < nch; c++) {
        if (c + 1 < nch) {
            issue(c + 1, (c + 1) & 1);
            asm volatile("cp.async.wait_group 1;");
        } else {
            asm volatile("cp.async.wait_group 0;");
        }
        __syncthreads();
        const float* dsm = Ds + (c & 1) * 4096;
        const float* xsm = Xs + (c & 1) * 512;
#pragma unroll
        for (int kq = 0; kq < 8; kq++) {
            ulonglong2 xv[4];
#pragma unroll
            for (int dk = 0; dk < 4; dk++)
                xv[dk] = *(const ulonglong2*)&xsm[(kq * 4 + dk) * 16 + q * 4];
#pragma unroll
            for (int j = 0; j < 4; j++) {
                int r = rl + 32 * j;
                float4 d = *(const float4*)&dsm[r * 32 + 4 * (kq ^ (r & 7))];
                ULL w0 = pk2(d.x), w1 = pk2(d.y), w2 = pk2(d.z), w3 = pk2(d.w);
                fma2(acc[j][0], w0, xv[0].x); fma2(acc[j][1], w0, xv[0].y);
                fma2(acc[j][0], w1, xv[1].x); fma2(acc[j][1], w1, xv[1].y);
                fma2(acc[j][0], w2, xv[2].x); fma2(acc[j][1], w2, xv[2].y);
                fma2(acc[j][0], w3, xv[3].x); fma2(acc[j][1], w3, xv[3].y);
            }
        }
        __syncthreads();
    }

    // accumulate straight into the output tensor (REDG, no partials)
    float* ob = out + ((size_t)b * M + (size_t)mt * 128) * 16;
#pragma unroll
    for (int j = 0; j < 4; j++) {
        float* p = ob + (rl + 32 * j) * 16 + q * 4;
        float2 a0 = up2(acc[j][0]);
        float2 a1 = up2(acc[j][1]);
        atomicAdd(p + 0, a0.x);
        atomicAdd(p + 1, a0.y);
        atomicAdd(p + 2, a1.x);
        atomicAdd(p + 3, a1.y);
    }
}

// ---------------- epilogue ----------------
__global__ void k_pool(const float* __restrict__ t, const float* __restrict__ mask) {
    __shared__ float ss[256], ms[256];
    int b = blockIdx.x;
    int ch = threadIdx.x & 63, g = threadIdx.x >> 6;
    float s = 0.f, m = 0.f;
    for (int n = g; n < 1024; n += 4) {
        float mv = mask[b * 1024 + n];
        s += t[((size_t)b * 1024 + n) * 64 + ch] * mv;
        m += mv;
    }
    ss[threadIdx.x] = s; ms[threadIdx.x] = m;
    __syncthreads();
    if (g == 0) {
#pragma unroll
        for (int j = 1; j < 4; j++) { s += ss[ch + 64 * j]; m += ms[ch + 64 * j]; }
        g_pool[b * 64 + ch] = s / m;
    }
}

__global__ void k_head(const float* __restrict__ Wfc, const float* __restrict__ bfc,
                       float* __restrict__ out) {
    __shared__ float lg[2][10];
    int tid = threadIdx.x;
    if (tid < 20) {
        int b = tid / 10, j = tid % 10;
        float acc = bfc[j];
        for (int ch = 0; ch < 64; ch++) acc = fmaf(g_pool[b * 64 + ch], Wfc[ch * 10 + j], acc);
        lg[b][j] = acc;
    }
    __syncthreads();
    if (tid < 20) {
        int b = tid / 10, j = tid % 10;
        float mx = -1e30f;
        for (int t = 0; t < 10; t++) mx = fmaxf(mx, lg[b][t]);
        float se = 0.f;
        for (int t = 0; t < 10; t++) se += expf(lg[b][t] - mx);
        out[b * 10 + j] = lg[b][j] - mx - logf(se);
    }
}

// ---------------- launcher ----------------
extern "C" void kernel_launch(void* const* d_in, const int* in_sizes, int n_in,
                              void* d_out, int out_size) {
    const float* inp  = (const float*)d_in[0];
    const float* Di   = (const float*)d_in[1];
    const float* DiA  = (const float*)d_in[2];
    const float* mask = (const float*)d_in[3];
    const float* W_in = (const float*)d_in[4];
    const float* b_in = (const float*)d_in[5];
    const float* rnW0 = (const float*)d_in[6];
    const float* rnb0 = (const float*)d_in[7];
    const float* rng0 = (const float*)d_in[8];
    const float* rnbe0= (const float*)d_in[9];
    const float* rnW1 = (const float*)d_in[10];
    const float* rnb1 = (const float*)d_in[11];
    const float* rng1 = (const float*)d_in[12];
    const float* rnbe1= (const float*)d_in[13];
    const float* bn2g = (const float*)d_in[14];
    const float* bn2b = (const float*)d_in[15];
    const float* W2   = (const float*)d_in[16];
    const float* b2   = (const float*)d_in[17];
    const float* Wfc  = (const float*)d_in[18];
    const float* bfc  = (const float*)d_in[19];
    float* out = (float*)d_out;

    float *v, *f, *X, *Y;
    cudaGetSymbolAddress((void**)&v, g_v);
    cudaGetSymbolAddress((void**)&f, g_f);
    cudaGetSymbolAddress((void**)&X, g_X);
    cudaGetSymbolAddress((void**)&Y, g_Y);

    const int SMEM = (8192 + 1024) * 4;                  // 36 KB dynamic
    cudaFuncSetAttribute(k_gemm, cudaFuncAttributeMaxDynamicSharedMemorySize, SMEM);

    k_init_v<<<256, 256>>>(inp, W_in, b_in);             // v + f zero + stats partials

    int nblk_v = 256;
    for (int i = 0; i < 5; i++) {
        // vertex -> face
        k_xform<<<128, 256>>>(v, rnW0 + i * 4096, rnb0 + i * 64,
                              rng0 + i * 64, rnbe0 + i * 64,
                              1.f / 2048.f, nblk_v, X);
        k_gemm<<<dim3(6, 64, 2), 128, SMEM>>>(Di, X, f, 8192, 4096, 128, 6);
        k_stats<<<64, 256>>>(f, 4096);
        // face -> vertex
        k_xform<<<256, 256>>>(f, rnW1 + i * 4096, rnb1 + i * 64,
                              rng1 + i * 64, rnbe1 + i * 64,
                              1.f / 4096.f, 64, Y);
        k_gemm<<<dim3(12, 32, 2), 128, SMEM>>>(DiA, Y, v, 4096, 8192, 256, 12);
        k_stats<<<64, 256>>>(v, 2048);
        nblk_v = 64;
    }

    // epilogue
    k_xform<<<128, 256>>>(v, W2, b2, bn2g, bn2b, 1.f / 2048.f, nblk_v, Y);
    k_pool<<<2, 256>>>(Y, mask);
    k_head<<<1, 32>>>(Wfc, bfc, out);
}